// round 5
// baseline (speedup 1.0000x reference)
#include <cuda_runtime.h>
#include <math.h>

// Problem constants
#define NN   50000
#define EE   800000
#define DIN  256
#define HH1  512
#define HH2  256
#define NC   5
#define NEG_SLOPE 0.2f

// ---------------------------------------------------------------------------
// Scratch (device globals; no allocation allowed). Resolved DEVICE-SIDE only.
// ---------------------------------------------------------------------------
__device__ float g_hcat1[(size_t)NN * 1024];  // [ x@W1 | x@A1+b1 ]   ld=1024
__device__ float g_h1   [(size_t)NN * HH1];   // relu(conv1 + lin1)
__device__ float g_hcat2[(size_t)NN * 512];   // [ h@W2 | h@A2+b2 ]   ld=512
__device__ float g_h2   [(size_t)NN * HH2];   // conv2 + lin2
__device__ float g_mlp0 [(size_t)NN * HH2];
__device__ float g_mlp1 [(size_t)NN * HH2];

__device__ float g_as[NN], g_ad[NN];
__device__ float g_m[NN], g_s[NN];
__device__ float g_w[EE];

__device__ int g_src[EE];
__device__ int g_dst[EE];
__device__ int g_is64;

__device__ int g_deg[NN];
__device__ int g_rowoff[NN + 1];
__device__ int g_fill[NN];
__device__ int g_csrc[EE];
__device__ int g_ceid[EE];

// Buffer ids
#define BUF_HCAT1 1
#define BUF_H1    2
#define BUF_HCAT2 3
#define BUF_H2    4
#define BUF_MLP0  5
#define BUF_MLP1  6

__device__ __forceinline__ float* scratch(int id)
{
    switch (id) {
        case BUF_HCAT1: return g_hcat1;
        case BUF_H1:    return g_h1;
        case BUF_HCAT2: return g_hcat2;
        case BUF_H2:    return g_h2;
        case BUF_MLP0:  return g_mlp0;
        case BUF_MLP1:  return g_mlp1;
        default:        return nullptr;
    }
}

// ---------------------------------------------------------------------------
// Edge-index dtype detection + conversion.
// If edge_index is int64 (little-endian), every entry's high word is 0 because
// all values lie in [0, 50000). If int32, odd raw words are regular edge
// entries — 64 consecutive zeros is astronomically unlikely.
// ---------------------------------------------------------------------------
__global__ void detect_dtype_kernel(const int* __restrict__ raw)
{
    int all_zero = 1;
    for (int k = 0; k < 64; k++)
        if (raw[2 * k + 1] != 0) { all_zero = 0; break; }
    g_is64 = all_zero;
}

__global__ void convert_edges_kernel(const int* __restrict__ raw)
{
    int e = blockIdx.x * blockDim.x + threadIdx.x;
    if (e >= EE) return;
    if (g_is64) {
        g_src[e] = raw[2 * e];               // low word of entry e
        g_dst[e] = raw[2 * (EE + e)];        // low word of entry EE+e
    } else {
        g_src[e] = raw[e];
        g_dst[e] = raw[EE + e];
    }
}

// ---------------------------------------------------------------------------
// SGEMM: C[M,N] = A[M,K] @ B[K,N] (+bias) (+relu).  Row-major, ldc given.
// BM=BN=128, BK=16, 256 threads, 8x8 per thread.  N%128==0, K%16==0, M ragged.
// ---------------------------------------------------------------------------
template <bool RELU, bool BIAS>
__global__ __launch_bounds__(256) void sgemm_kernel(
    const float* __restrict__ Aext, int Aid,
    const float* __restrict__ B, const float* __restrict__ bias,
    int Cid, int coff,
    int M, int N, int K, int ldc)
{
    const float* A = Aext ? Aext : scratch(Aid);
    float* C = scratch(Cid) + coff;

    const int BM = 128, BN = 128, BK = 16;
    __shared__ float As[BK][BM];
    __shared__ float Bs[BK][BN];

    int tid = threadIdx.x;
    int tx = tid & 15;       // 0..15 -> col group
    int ty = tid >> 4;       // 0..15 -> row group
    int row0 = blockIdx.y * BM;
    int col0 = blockIdx.x * BN;

    float acc[8][8];
#pragma unroll
    for (int m = 0; m < 8; m++)
#pragma unroll
        for (int n = 0; n < 8; n++) acc[m][n] = 0.f;

    for (int k0 = 0; k0 < K; k0 += BK) {
        // Load A tile (128 x 16): 512 float4, 2 per thread, transpose into As
#pragma unroll
        for (int i = 0; i < 2; i++) {
            int idx = tid + i * 256;
            int r = idx >> 2;       // 0..127
            int c4 = idx & 3;       // 0..3
            float4 v = make_float4(0.f, 0.f, 0.f, 0.f);
            if (row0 + r < M)
                v = *(const float4*)(A + (size_t)(row0 + r) * K + k0 + c4 * 4);
            As[c4 * 4 + 0][r] = v.x;
            As[c4 * 4 + 1][r] = v.y;
            As[c4 * 4 + 2][r] = v.z;
            As[c4 * 4 + 3][r] = v.w;
        }
        // Load B tile (16 x 128): 512 float4, 2 per thread
#pragma unroll
        for (int i = 0; i < 2; i++) {
            int idx = tid + i * 256;
            int r = idx >> 5;       // 0..15
            int c4 = idx & 31;      // 0..31
            float4 v = *(const float4*)(B + (size_t)(k0 + r) * N + col0 + c4 * 4);
            *(float4*)(&Bs[r][c4 * 4]) = v;
        }
        __syncthreads();

#pragma unroll
        for (int kk = 0; kk < BK; kk++) {
            float4 a0 = *(const float4*)(&As[kk][ty * 8]);
            float4 a1 = *(const float4*)(&As[kk][ty * 8 + 4]);
            float4 b0 = *(const float4*)(&Bs[kk][tx * 8]);
            float4 b1 = *(const float4*)(&Bs[kk][tx * 8 + 4]);
            float ra[8] = {a0.x, a0.y, a0.z, a0.w, a1.x, a1.y, a1.z, a1.w};
            float rb[8] = {b0.x, b0.y, b0.z, b0.w, b1.x, b1.y, b1.z, b1.w};
#pragma unroll
            for (int m = 0; m < 8; m++)
#pragma unroll
                for (int n = 0; n < 8; n++) acc[m][n] += ra[m] * rb[n];
        }
        __syncthreads();
    }

#pragma unroll
    for (int m = 0; m < 8; m++) {
        int r = row0 + ty * 8 + m;
        if (r >= M) continue;
#pragma unroll
        for (int n = 0; n < 8; n += 4) {
            int c = col0 + tx * 8 + n;
            float4 v = make_float4(acc[m][n], acc[m][n + 1], acc[m][n + 2], acc[m][n + 3]);
            if (BIAS) {
                v.x += bias[c];
                v.y += bias[c + 1];
                v.z += bias[c + 2];
                v.w += bias[c + 3];
            }
            if (RELU) {
                v.x = fmaxf(v.x, 0.f);
                v.y = fmaxf(v.y, 0.f);
                v.z = fmaxf(v.z, 0.f);
                v.w = fmaxf(v.w, 0.f);
            }
            *(float4*)(C + (size_t)r * ldc + c) = v;
        }
    }
}

// ---------------------------------------------------------------------------
// Attention dot products: warp per node.
// ---------------------------------------------------------------------------
__global__ void att_dots_kernel(int hid, int C, int ld,
                                const float* __restrict__ asv,
                                const float* __restrict__ adv)
{
    const float* h = scratch(hid);
    int warp = (blockIdx.x * blockDim.x + threadIdx.x) >> 5;
    int lane = threadIdx.x & 31;
    if (warp >= NN) return;
    const float* row = h + (size_t)warp * ld;
    float s1 = 0.f, s2 = 0.f;
    for (int c = lane; c < C; c += 32) {
        float v = row[c];
        s1 += v * asv[c];
        s2 += v * adv[c];
    }
#pragma unroll
    for (int o = 16; o; o >>= 1) {
        s1 += __shfl_xor_sync(0xffffffffu, s1, o);
        s2 += __shfl_xor_sync(0xffffffffu, s2, o);
    }
    if (lane == 0) { g_as[warp] = s1; g_ad[warp] = s2; }
}

// ---------------------------------------------------------------------------
// CSR build
// ---------------------------------------------------------------------------
__global__ void init_csr_kernel()
{
    int i = blockIdx.x * blockDim.x + threadIdx.x;
    if (i < NN) { g_deg[i] = 0; g_fill[i] = 0; }
}

__global__ void init_ms_kernel()
{
    int i = blockIdx.x * blockDim.x + threadIdx.x;
    if (i < NN) { g_m[i] = -1e30f; g_s[i] = 0.f; }
}

__global__ void hist_kernel()
{
    int e = blockIdx.x * blockDim.x + threadIdx.x;
    if (e < EE) atomicAdd(&g_deg[g_dst[e]], 1);
}

// Single-block exclusive scan of g_deg -> g_rowoff (NN+1 entries)
__global__ __launch_bounds__(1024) void scan_kernel()
{
    __shared__ int wsum[32];
    __shared__ int running;
    int tid = threadIdx.x;
    int lane = tid & 31, wid = tid >> 5;
    if (tid == 0) running = 0;
    __syncthreads();
    for (int base = 0; base < NN; base += 1024) {
        int i = base + tid;
        int v = (i < NN) ? g_deg[i] : 0;
        int x = v;
#pragma unroll
        for (int o = 1; o < 32; o <<= 1) {
            int y = __shfl_up_sync(0xffffffffu, x, o);
            if (lane >= o) x += y;
        }
        if (lane == 31) wsum[wid] = x;
        __syncthreads();
        if (wid == 0) {
            int w = wsum[lane];
#pragma unroll
            for (int o = 1; o < 32; o <<= 1) {
                int y = __shfl_up_sync(0xffffffffu, w, o);
                if (lane >= o) w += y;
            }
            wsum[lane] = w;
        }
        __syncthreads();
        int excl = x - v + (wid > 0 ? wsum[wid - 1] : 0);
        if (i < NN) g_rowoff[i] = running + excl;
        int total = wsum[31];
        __syncthreads();
        if (tid == 0) running += total;
        __syncthreads();
    }
    if (tid == 0) g_rowoff[NN] = running;
}

__global__ void fill_kernel()
{
    int e = blockIdx.x * blockDim.x + threadIdx.x;
    if (e < EE) {
        int d = g_dst[e];
        int p = g_rowoff[d] + atomicAdd(&g_fill[d], 1);
        g_csrc[p] = g_src[e];
        g_ceid[p] = e;
    }
}

// ---------------------------------------------------------------------------
// Edge softmax
// ---------------------------------------------------------------------------
__device__ __forceinline__ void atomicMaxF(float* addr, float val)
{
    int old = __float_as_int(*addr);
    while (__int_as_float(old) < val) {
        int assumed = old;
        old = atomicCAS((int*)addr, assumed, __float_as_int(val));
        if (old == assumed) break;
    }
}

__global__ void edge_max_kernel()
{
    int e = blockIdx.x * blockDim.x + threadIdx.x;
    if (e >= EE) return;
    float t = g_as[g_src[e]] + g_ad[g_dst[e]];
    t = (t > 0.f) ? t : NEG_SLOPE * t;   // leaky relu
    g_w[e] = t;
    atomicMaxF(&g_m[g_dst[e]], t);
}

__global__ void edge_exp_kernel()
{
    int e = blockIdx.x * blockDim.x + threadIdx.x;
    if (e >= EE) return;
    int d = g_dst[e];
    float w = expf(g_w[e] - g_m[d]);
    g_w[e] = w;
    atomicAdd(&g_s[d], w);
}

// ---------------------------------------------------------------------------
// Aggregation: block per dst node, C/4 threads, one float4 per thread.
// out[n] = (sum_e w[e]*h[src_e]) / (s[n]+eps) + res[n] + bias   (optional relu)
// ---------------------------------------------------------------------------
template <int C, bool RELU>
__global__ void aggregate_kernel(int hid, int hoff, int roff, int ldh,
                                 const float* __restrict__ bias, int oid)
{
    const float* base = scratch(hid);
    const float* h = base + hoff;
    const float* res = base + roff;
    float* out = scratch(oid);

    int n = blockIdx.x;
    int t4 = threadIdx.x * 4;           // column offset
    int beg = g_rowoff[n], end = g_rowoff[n + 1];
    float inv = 1.0f / (g_s[n] + 1e-16f);
    float4 acc = make_float4(0.f, 0.f, 0.f, 0.f);
    int j = beg;
    for (; j + 1 < end; j += 2) {
        int s0 = g_csrc[j], s1 = g_csrc[j + 1];
        float c0 = g_w[g_ceid[j]] * inv;
        float c1 = g_w[g_ceid[j + 1]] * inv;
        float4 h0 = *(const float4*)(h + (size_t)s0 * ldh + t4);
        float4 h1 = *(const float4*)(h + (size_t)s1 * ldh + t4);
        acc.x += c0 * h0.x + c1 * h1.x;
        acc.y += c0 * h0.y + c1 * h1.y;
        acc.z += c0 * h0.z + c1 * h1.z;
        acc.w += c0 * h0.w + c1 * h1.w;
    }
    if (j < end) {
        int s0 = g_csrc[j];
        float c0 = g_w[g_ceid[j]] * inv;
        float4 h0 = *(const float4*)(h + (size_t)s0 * ldh + t4);
        acc.x += c0 * h0.x;
        acc.y += c0 * h0.y;
        acc.z += c0 * h0.z;
        acc.w += c0 * h0.w;
    }
    float4 r = *(const float4*)(res + (size_t)n * ldh + t4);
    float4 o;
    o.x = acc.x + r.x + bias[t4 + 0];
    o.y = acc.y + r.y + bias[t4 + 1];
    o.z = acc.z + r.z + bias[t4 + 2];
    o.w = acc.w + r.w + bias[t4 + 3];
    if (RELU) {
        o.x = fmaxf(o.x, 0.f);
        o.y = fmaxf(o.y, 0.f);
        o.z = fmaxf(o.z, 0.f);
        o.w = fmaxf(o.w, 0.f);
    }
    *(float4*)(out + (size_t)n * C + t4) = o;
}

// ---------------------------------------------------------------------------
// Classifier + softmax: warp per node.
// ---------------------------------------------------------------------------
__global__ void fc_softmax_kernel(int hid,
                                  const float* __restrict__ fcw,
                                  const float* __restrict__ fcb,
                                  float* __restrict__ out)
{
    const float* h = scratch(hid);
    int warp = (blockIdx.x * blockDim.x + threadIdx.x) >> 5;
    int lane = threadIdx.x & 31;
    if (warp >= NN) return;
    const float* row = h + (size_t)warp * HH2;
    float acc[NC] = {0.f, 0.f, 0.f, 0.f, 0.f};
    for (int c = lane; c < HH2; c += 32) {
        float v = row[c];
#pragma unroll
        for (int j = 0; j < NC; j++) acc[j] += v * fcw[c * NC + j];
    }
#pragma unroll
    for (int j = 0; j < NC; j++)
#pragma unroll
        for (int o = 16; o; o >>= 1)
            acc[j] += __shfl_xor_sync(0xffffffffu, acc[j], o);
    if (lane == 0) {
        float mx = -1e30f;
#pragma unroll
        for (int j = 0; j < NC; j++) {
            acc[j] += fcb[j];
            mx = fmaxf(mx, acc[j]);
        }
        float s = 0.f;
#pragma unroll
        for (int j = 0; j < NC; j++) {
            acc[j] = expf(acc[j] - mx);
            s += acc[j];
        }
        float invs = 1.0f / s;
#pragma unroll
        for (int j = 0; j < NC; j++) out[(size_t)warp * NC + j] = acc[j] * invs;
    }
}

// ---------------------------------------------------------------------------
// Launch
// ---------------------------------------------------------------------------
static inline void run_gemm(const float* Aext, int Aid,
                            const float* B, const float* bias,
                            int Cid, int coff,
                            int M, int N, int K, int ldc,
                            bool relu, cudaStream_t st)
{
    dim3 grid(N / 128, (M + 127) / 128);
    if (relu) {
        if (bias) sgemm_kernel<true, true><<<grid, 256, 0, st>>>(Aext, Aid, B, bias, Cid, coff, M, N, K, ldc);
        else      sgemm_kernel<true, false><<<grid, 256, 0, st>>>(Aext, Aid, B, bias, Cid, coff, M, N, K, ldc);
    } else {
        if (bias) sgemm_kernel<false, true><<<grid, 256, 0, st>>>(Aext, Aid, B, bias, Cid, coff, M, N, K, ldc);
        else      sgemm_kernel<false, false><<<grid, 256, 0, st>>>(Aext, Aid, B, bias, Cid, coff, M, N, K, ldc);
    }
}

extern "C" void kernel_launch(void* const* d_in, const int* in_sizes, int n_in,
                              void* d_out, int out_size)
{
    const float* x        = (const float*)d_in[0];
    const int*   ei_raw   = (const int*)d_in[1];   // int32 or int64 — detected on device
    const float* W1       = (const float*)d_in[2];
    const float* att_src1 = (const float*)d_in[3];
    const float* att_dst1 = (const float*)d_in[4];
    const float* b_conv1  = (const float*)d_in[5];
    const float* A1       = (const float*)d_in[6];
    const float* b1       = (const float*)d_in[7];
    const float* W2       = (const float*)d_in[8];
    const float* att_src2 = (const float*)d_in[9];
    const float* att_dst2 = (const float*)d_in[10];
    const float* b_conv2  = (const float*)d_in[11];
    const float* A2       = (const float*)d_in[12];
    const float* b2       = (const float*)d_in[13];
    const float* Hw1      = (const float*)d_in[14];
    const float* Hb1      = (const float*)d_in[15];
    const float* Hw2      = (const float*)d_in[16];
    const float* Hb2      = (const float*)d_in[17];
    const float* Hw3      = (const float*)d_in[18];
    const float* Hb3      = (const float*)d_in[19];
    const float* fcw      = (const float*)d_in[20];
    const float* fcb      = (const float*)d_in[21];
    float*       out      = (float*)d_out;

    cudaStream_t st = 0;  // default stream (captured by harness)

    const int NB = (NN + 255) / 256;
    const int EB = (EE + 255) / 256;
    const int WB = (NN * 32 + 255) / 256;  // warp-per-node kernels

    // ---- Edge decode (dtype-agnostic) + CSR build (once per launch) ----
    detect_dtype_kernel<<<1, 1, 0, st>>>(ei_raw);
    convert_edges_kernel<<<EB, 256, 0, st>>>(ei_raw);
    init_csr_kernel<<<NB, 256, 0, st>>>();
    hist_kernel<<<EB, 256, 0, st>>>();
    scan_kernel<<<1, 1024, 0, st>>>();
    fill_kernel<<<EB, 256, 0, st>>>();

    // ---- Layer 1: hcat1 = [x@W1 | x@A1+b1] ----
    run_gemm(x, 0, W1, nullptr, BUF_HCAT1, 0,   NN, HH1, DIN, 1024, false, st);
    run_gemm(x, 0, A1, b1,      BUF_HCAT1, HH1, NN, HH1, DIN, 1024, false, st);
    att_dots_kernel<<<WB, 256, 0, st>>>(BUF_HCAT1, HH1, 1024, att_src1, att_dst1);
    init_ms_kernel<<<NB, 256, 0, st>>>();
    edge_max_kernel<<<EB, 256, 0, st>>>();
    edge_exp_kernel<<<EB, 256, 0, st>>>();
    aggregate_kernel<HH1, true><<<NN, HH1 / 4, 0, st>>>(
        BUF_HCAT1, 0, HH1, 1024, b_conv1, BUF_H1);

    // ---- Layer 2: hcat2 = [h1@W2 | h1@A2+b2] ----
    run_gemm(nullptr, BUF_H1, W2, nullptr, BUF_HCAT2, 0,   NN, HH2, HH1, 512, false, st);
    run_gemm(nullptr, BUF_H1, A2, b2,      BUF_HCAT2, HH2, NN, HH2, HH1, 512, false, st);
    att_dots_kernel<<<WB, 256, 0, st>>>(BUF_HCAT2, HH2, 512, att_src2, att_dst2);
    init_ms_kernel<<<NB, 256, 0, st>>>();
    edge_max_kernel<<<EB, 256, 0, st>>>();
    edge_exp_kernel<<<EB, 256, 0, st>>>();
    aggregate_kernel<HH2, false><<<NN, HH2 / 4, 0, st>>>(
        BUF_HCAT2, 0, HH2, 512, b_conv2, BUF_H2);

    // ---- MLP ----
    run_gemm(nullptr, BUF_H2,   Hw1, Hb1, BUF_MLP0, 0, NN, HH2, HH2, HH2, true, st);
    run_gemm(nullptr, BUF_MLP0, Hw2, Hb2, BUF_MLP1, 0, NN, HH2, HH2, HH2, true, st);
    run_gemm(nullptr, BUF_MLP1, Hw3, Hb3, BUF_MLP0, 0, NN, HH2, HH2, HH2, true, st);

    // ---- Classifier + softmax ----
    fc_softmax_kernel<<<WB, 256, 0, st>>>(BUF_MLP0, fcw, fcb, out);
}

// round 10
// speedup vs baseline: 1.0174x; 1.0174x over previous
#include <cuda_runtime.h>
#include <math.h>

// Problem constants
#define NN   50000
#define EE   800000
#define DIN  256
#define HH1  512
#define HH2  256
#define NC   5
#define NEG_SLOPE 0.2f

typedef unsigned long long u64;

// ---------------------------------------------------------------------------
// Packed f32x2 helpers (Blackwell sm_103a; FFMA2 only reachable via PTX)
// ---------------------------------------------------------------------------
__device__ __forceinline__ u64 pack2(float lo, float hi)
{
    u64 r;
    asm("mov.b64 %0, {%1, %2};" : "=l"(r) : "f"(lo), "f"(hi));
    return r;
}
__device__ __forceinline__ void ffma2(u64& acc, u64 a, u64 b)
{
    asm("fma.rn.f32x2 %0, %1, %2, %0;" : "+l"(acc) : "l"(a), "l"(b));
}
__device__ __forceinline__ float2 unpack2(u64 v)
{
    float2 f;
    asm("mov.b64 {%0, %1}, %2;" : "=f"(f.x), "=f"(f.y) : "l"(v));
    return f;
}

// ---------------------------------------------------------------------------
// Scratch (device globals; no allocation allowed). Resolved DEVICE-SIDE only.
// ---------------------------------------------------------------------------
__device__ float g_hcat1[(size_t)NN * 1024];  // [ x@W1 | x@A1+b1 ]   ld=1024
__device__ float g_h1   [(size_t)NN * HH1];   // relu(conv1 + lin1)
__device__ float g_hcat2[(size_t)NN * 512];   // [ h@W2 | h@A2+b2 ]   ld=512
__device__ float g_h2   [(size_t)NN * HH2];   // conv2 + lin2
__device__ float g_mlp0 [(size_t)NN * HH2];
__device__ float g_mlp1 [(size_t)NN * HH2];

__device__ float g_as[NN], g_ad[NN];
__device__ float g_m[NN], g_s[NN];
__device__ float g_w[EE];

__device__ int g_src[EE];
__device__ int g_dst[EE];
__device__ int g_is64;

__device__ int g_deg[NN];
__device__ int g_rowoff[NN + 1];
__device__ int g_fill[NN];
__device__ int g_csrc[EE];
__device__ int g_ceid[EE];

// Buffer ids
#define BUF_HCAT1 1
#define BUF_H1    2
#define BUF_HCAT2 3
#define BUF_H2    4
#define BUF_MLP0  5
#define BUF_MLP1  6

__device__ __forceinline__ float* scratch(int id)
{
    switch (id) {
        case BUF_HCAT1: return g_hcat1;
        case BUF_H1:    return g_h1;
        case BUF_HCAT2: return g_hcat2;
        case BUF_H2:    return g_h2;
        case BUF_MLP0:  return g_mlp0;
        case BUF_MLP1:  return g_mlp1;
        default:        return nullptr;
    }
}

// ---------------------------------------------------------------------------
// Edge-index dtype detection + conversion.
// ---------------------------------------------------------------------------
__global__ void detect_dtype_kernel(const int* __restrict__ raw)
{
    int all_zero = 1;
    for (int k = 0; k < 64; k++)
        if (raw[2 * k + 1] != 0) { all_zero = 0; break; }
    g_is64 = all_zero;
}

__global__ void convert_edges_kernel(const int* __restrict__ raw)
{
    int e = blockIdx.x * blockDim.x + threadIdx.x;
    if (e >= EE) return;
    if (g_is64) {
        g_src[e] = raw[2 * e];
        g_dst[e] = raw[2 * (EE + e)];
    } else {
        g_src[e] = raw[e];
        g_dst[e] = raw[EE + e];
    }
}

// ---------------------------------------------------------------------------
// SGEMM: C[M,N] = A[M,K] @ B[K,N] (+bias) (+relu).  Row-major, ldc given.
// BM=BN=128, BK=16, 256 threads, 8x8 per thread.
// Inner product uses packed fma.rn.f32x2: 32 FFMA2 per k-step instead of
// 64 FFMA.  Accumulators: 8 M-rows x 4 N-pairs of f32x2.
// ---------------------------------------------------------------------------
template <bool RELU, bool BIAS>
__global__ __launch_bounds__(256) void sgemm_kernel(
    const float* __restrict__ Aext, int Aid,
    const float* __restrict__ B, const float* __restrict__ bias,
    int Cid, int coff,
    int M, int N, int K, int ldc)
{
    const float* A = Aext ? Aext : scratch(Aid);
    float* C = scratch(Cid) + coff;

    const int BM = 128, BN = 128, BK = 16;
    __shared__ float As[BK][BM];
    __shared__ float Bs[BK][BN];

    int tid = threadIdx.x;
    int tx = tid & 15;       // 0..15 -> col group (8 cols each)
    int ty = tid >> 4;       // 0..15 -> row group (8 rows each)
    int row0 = blockIdx.y * BM;
    int col0 = blockIdx.x * BN;

    u64 acc2[8][4];
#pragma unroll
    for (int m = 0; m < 8; m++)
#pragma unroll
        for (int j = 0; j < 4; j++) acc2[m][j] = 0ull;

    for (int k0 = 0; k0 < K; k0 += BK) {
        // Load A tile (128 x 16): 512 float4, 2 per thread, transpose into As
#pragma unroll
        for (int i = 0; i < 2; i++) {
            int idx = tid + i * 256;
            int r = idx >> 2;       // 0..127
            int c4 = idx & 3;       // 0..3
            float4 v = make_float4(0.f, 0.f, 0.f, 0.f);
            if (row0 + r < M)
                v = *(const float4*)(A + (size_t)(row0 + r) * K + k0 + c4 * 4);
            As[c4 * 4 + 0][r] = v.x;
            As[c4 * 4 + 1][r] = v.y;
            As[c4 * 4 + 2][r] = v.z;
            As[c4 * 4 + 3][r] = v.w;
        }
        // Load B tile (16 x 128): 512 float4, 2 per thread
#pragma unroll
        for (int i = 0; i < 2; i++) {
            int idx = tid + i * 256;
            int r = idx >> 5;       // 0..15
            int c4 = idx & 31;      // 0..31
            float4 v = *(const float4*)(B + (size_t)(k0 + r) * N + col0 + c4 * 4);
            *(float4*)(&Bs[r][c4 * 4]) = v;
        }
        __syncthreads();

#pragma unroll
        for (int kk = 0; kk < BK; kk++) {
            // A fragment: 8 scalars (broadcast across the f32x2 lanes)
            float4 a0 = *(const float4*)(&As[kk][ty * 8]);
            float4 a1 = *(const float4*)(&As[kk][ty * 8 + 4]);
            float ra[8] = {a0.x, a0.y, a0.z, a0.w, a1.x, a1.y, a1.z, a1.w};
            // B fragment: 4 packed pairs, read directly as 64-bit
            ulonglong2 bb0 = *(const ulonglong2*)(&Bs[kk][tx * 8]);
            ulonglong2 bb1 = *(const ulonglong2*)(&Bs[kk][tx * 8 + 4]);
            u64 rb[4] = {bb0.x, bb0.y, bb1.x, bb1.y};
#pragma unroll
            for (int m = 0; m < 8; m++) {
                u64 am = pack2(ra[m], ra[m]);
#pragma unroll
                for (int j = 0; j < 4; j++) ffma2(acc2[m][j], am, rb[j]);
            }
        }
        __syncthreads();
    }

#pragma unroll
    for (int m = 0; m < 8; m++) {
        int r = row0 + ty * 8 + m;
        if (r >= M) continue;
#pragma unroll
        for (int half = 0; half < 2; half++) {
            int c = col0 + tx * 8 + half * 4;
            float2 p0 = unpack2(acc2[m][half * 2 + 0]);
            float2 p1 = unpack2(acc2[m][half * 2 + 1]);
            float4 v = make_float4(p0.x, p0.y, p1.x, p1.y);
            if (BIAS) {
                v.x += bias[c];
                v.y += bias[c + 1];
                v.z += bias[c + 2];
                v.w += bias[c + 3];
            }
            if (RELU) {
                v.x = fmaxf(v.x, 0.f);
                v.y = fmaxf(v.y, 0.f);
                v.z = fmaxf(v.z, 0.f);
                v.w = fmaxf(v.w, 0.f);
            }
            *(float4*)(C + (size_t)r * ldc + c) = v;
        }
    }
}

// ---------------------------------------------------------------------------
// Attention dot products: warp per node.
// ---------------------------------------------------------------------------
__global__ void att_dots_kernel(int hid, int C, int ld,
                                const float* __restrict__ asv,
                                const float* __restrict__ adv)
{
    const float* h = scratch(hid);
    int warp = (blockIdx.x * blockDim.x + threadIdx.x) >> 5;
    int lane = threadIdx.x & 31;
    if (warp >= NN) return;
    const float* row = h + (size_t)warp * ld;
    float s1 = 0.f, s2 = 0.f;
    for (int c = lane; c < C; c += 32) {
        float v = row[c];
        s1 += v * asv[c];
        s2 += v * adv[c];
    }
#pragma unroll
    for (int o = 16; o; o >>= 1) {
        s1 += __shfl_xor_sync(0xffffffffu, s1, o);
        s2 += __shfl_xor_sync(0xffffffffu, s2, o);
    }
    if (lane == 0) { g_as[warp] = s1; g_ad[warp] = s2; }
}

// ---------------------------------------------------------------------------
// CSR build
// ---------------------------------------------------------------------------
__global__ void init_csr_kernel()
{
    int i = blockIdx.x * blockDim.x + threadIdx.x;
    if (i < NN) { g_deg[i] = 0; g_fill[i] = 0; }
}

__global__ void init_ms_kernel()
{
    int i = blockIdx.x * blockDim.x + threadIdx.x;
    if (i < NN) { g_m[i] = -1e30f; g_s[i] = 0.f; }
}

__global__ void hist_kernel()
{
    int e = blockIdx.x * blockDim.x + threadIdx.x;
    if (e < EE) atomicAdd(&g_deg[g_dst[e]], 1);
}

// Single-block exclusive scan of g_deg -> g_rowoff (NN+1 entries)
__global__ __launch_bounds__(1024) void scan_kernel()
{
    __shared__ int wsum[32];
    __shared__ int running;
    int tid = threadIdx.x;
    int lane = tid & 31, wid = tid >> 5;
    if (tid == 0) running = 0;
    __syncthreads();
    for (int base = 0; base < NN; base += 1024) {
        int i = base + tid;
        int v = (i < NN) ? g_deg[i] : 0;
        int x = v;
#pragma unroll
        for (int o = 1; o < 32; o <<= 1) {
            int y = __shfl_up_sync(0xffffffffu, x, o);
            if (lane >= o) x += y;
        }
        if (lane == 31) wsum[wid] = x;
        __syncthreads();
        if (wid == 0) {
            int w = wsum[lane];
#pragma unroll
            for (int o = 1; o < 32; o <<= 1) {
                int y = __shfl_up_sync(0xffffffffu, w, o);
                if (lane >= o) w += y;
            }
            wsum[lane] = w;
        }
        __syncthreads();
        int excl = x - v + (wid > 0 ? wsum[wid - 1] : 0);
        if (i < NN) g_rowoff[i] = running + excl;
        int total = wsum[31];
        __syncthreads();
        if (tid == 0) running += total;
        __syncthreads();
    }
    if (tid == 0) g_rowoff[NN] = running;
}

__global__ void fill_kernel()
{
    int e = blockIdx.x * blockDim.x + threadIdx.x;
    if (e < EE) {
        int d = g_dst[e];
        int p = g_rowoff[d] + atomicAdd(&g_fill[d], 1);
        g_csrc[p] = g_src[e];
        g_ceid[p] = e;
    }
}

// ---------------------------------------------------------------------------
// Edge softmax
// ---------------------------------------------------------------------------
__device__ __forceinline__ void atomicMaxF(float* addr, float val)
{
    int old = __float_as_int(*addr);
    while (__int_as_float(old) < val) {
        int assumed = old;
        old = atomicCAS((int*)addr, assumed, __float_as_int(val));
        if (old == assumed) break;
    }
}

__global__ void edge_max_kernel()
{
    int e = blockIdx.x * blockDim.x + threadIdx.x;
    if (e >= EE) return;
    float t = g_as[g_src[e]] + g_ad[g_dst[e]];
    t = (t > 0.f) ? t : NEG_SLOPE * t;   // leaky relu
    g_w[e] = t;
    atomicMaxF(&g_m[g_dst[e]], t);
}

__global__ void edge_exp_kernel()
{
    int e = blockIdx.x * blockDim.x + threadIdx.x;
    if (e >= EE) return;
    int d = g_dst[e];
    float w = expf(g_w[e] - g_m[d]);
    g_w[e] = w;
    atomicAdd(&g_s[d], w);
}

// ---------------------------------------------------------------------------
// Aggregation: block per dst node, C/4 threads, one float4 per thread.
// ---------------------------------------------------------------------------
template <int C, bool RELU>
__global__ void aggregate_kernel(int hid, int hoff, int roff, int ldh,
                                 const float* __restrict__ bias, int oid)
{
    const float* base = scratch(hid);
    const float* h = base + hoff;
    const float* res = base + roff;
    float* out = scratch(oid);

    int n = blockIdx.x;
    int t4 = threadIdx.x * 4;           // column offset
    int beg = g_rowoff[n], end = g_rowoff[n + 1];
    float inv = 1.0f / (g_s[n] + 1e-16f);
    float4 acc = make_float4(0.f, 0.f, 0.f, 0.f);
    int j = beg;
    for (; j + 1 < end; j += 2) {
        int s0 = g_csrc[j], s1 = g_csrc[j + 1];
        float c0 = g_w[g_ceid[j]] * inv;
        float c1 = g_w[g_ceid[j + 1]] * inv;
        float4 h0 = *(const float4*)(h + (size_t)s0 * ldh + t4);
        float4 h1 = *(const float4*)(h + (size_t)s1 * ldh + t4);
        acc.x += c0 * h0.x + c1 * h1.x;
        acc.y += c0 * h0.y + c1 * h1.y;
        acc.z += c0 * h0.z + c1 * h1.z;
        acc.w += c0 * h0.w + c1 * h1.w;
    }
    if (j < end) {
        int s0 = g_csrc[j];
        float c0 = g_w[g_ceid[j]] * inv;
        float4 h0 = *(const float4*)(h + (size_t)s0 * ldh + t4);
        acc.x += c0 * h0.x;
        acc.y += c0 * h0.y;
        acc.z += c0 * h0.z;
        acc.w += c0 * h0.w;
    }
    float4 r = *(const float4*)(res + (size_t)n * ldh + t4);
    float4 o;
    o.x = acc.x + r.x + bias[t4 + 0];
    o.y = acc.y + r.y + bias[t4 + 1];
    o.z = acc.z + r.z + bias[t4 + 2];
    o.w = acc.w + r.w + bias[t4 + 3];
    if (RELU) {
        o.x = fmaxf(o.x, 0.f);
        o.y = fmaxf(o.y, 0.f);
        o.z = fmaxf(o.z, 0.f);
        o.w = fmaxf(o.w, 0.f);
    }
    *(float4*)(out + (size_t)n * C + t4) = o;
}

// ---------------------------------------------------------------------------
// Classifier + softmax: warp per node.
// ---------------------------------------------------------------------------
__global__ void fc_softmax_kernel(int hid,
                                  const float* __restrict__ fcw,
                                  const float* __restrict__ fcb,
                                  float* __restrict__ out)
{
    const float* h = scratch(hid);
    int warp = (blockIdx.x * blockDim.x + threadIdx.x) >> 5;
    int lane = threadIdx.x & 31;
    if (warp >= NN) return;
    const float* row = h + (size_t)warp * HH2;
    float acc[NC] = {0.f, 0.f, 0.f, 0.f, 0.f};
    for (int c = lane; c < HH2; c += 32) {
        float v = row[c];
#pragma unroll
        for (int j = 0; j < NC; j++) acc[j] += v * fcw[c * NC + j];
    }
#pragma unroll
    for (int j = 0; j < NC; j++)
#pragma unroll
        for (int o = 16; o; o >>= 1)
            acc[j] += __shfl_xor_sync(0xffffffffu, acc[j], o);
    if (lane == 0) {
        float mx = -1e30f;
#pragma unroll
        for (int j = 0; j < NC; j++) {
            acc[j] += fcb[j];
            mx = fmaxf(mx, acc[j]);
        }
        float s = 0.f;
#pragma unroll
        for (int j = 0; j < NC; j++) {
            acc[j] = expf(acc[j] - mx);
            s += acc[j];
        }
        float invs = 1.0f / s;
#pragma unroll
        for (int j = 0; j < NC; j++) out[(size_t)warp * NC + j] = acc[j] * invs;
    }
}

// ---------------------------------------------------------------------------
// Launch
// ---------------------------------------------------------------------------
static inline void run_gemm(const float* Aext, int Aid,
                            const float* B, const float* bias,
                            int Cid, int coff,
                            int M, int N, int K, int ldc,
                            bool relu, cudaStream_t st)
{
    dim3 grid(N / 128, (M + 127) / 128);
    if (relu) {
        if (bias) sgemm_kernel<true, true><<<grid, 256, 0, st>>>(Aext, Aid, B, bias, Cid, coff, M, N, K, ldc);
        else      sgemm_kernel<true, false><<<grid, 256, 0, st>>>(Aext, Aid, B, bias, Cid, coff, M, N, K, ldc);
    } else {
        if (bias) sgemm_kernel<false, true><<<grid, 256, 0, st>>>(Aext, Aid, B, bias, Cid, coff, M, N, K, ldc);
        else      sgemm_kernel<false, false><<<grid, 256, 0, st>>>(Aext, Aid, B, bias, Cid, coff, M, N, K, ldc);
    }
}

extern "C" void kernel_launch(void* const* d_in, const int* in_sizes, int n_in,
                              void* d_out, int out_size)
{
    const float* x        = (const float*)d_in[0];
    const int*   ei_raw   = (const int*)d_in[1];   // int32 or int64 — detected on device
    const float* W1       = (const float*)d_in[2];
    const float* att_src1 = (const float*)d_in[3];
    const float* att_dst1 = (const float*)d_in[4];
    const float* b_conv1  = (const float*)d_in[5];
    const float* A1       = (const float*)d_in[6];
    const float* b1       = (const float*)d_in[7];
    const float* W2       = (const float*)d_in[8];
    const float* att_src2 = (const float*)d_in[9];
    const float* att_dst2 = (const float*)d_in[10];
    const float* b_conv2  = (const float*)d_in[11];
    const float* A2       = (const float*)d_in[12];
    const float* b2       = (const float*)d_in[13];
    const float* Hw1      = (const float*)d_in[14];
    const float* Hb1      = (const float*)d_in[15];
    const float* Hw2      = (const float*)d_in[16];
    const float* Hb2      = (const float*)d_in[17];
    const float* Hw3      = (const float*)d_in[18];
    const float* Hb3      = (const float*)d_in[19];
    const float* fcw      = (const float*)d_in[20];
    const float* fcb      = (const float*)d_in[21];
    float*       out      = (float*)d_out;

    cudaStream_t st = 0;  // default stream (captured by harness)

    const int NB = (NN + 255) / 256;
    const int EB = (EE + 255) / 256;
    const int WB = (NN * 32 + 255) / 256;  // warp-per-node kernels

    // ---- Edge decode (dtype-agnostic) + CSR build (once per launch) ----
    detect_dtype_kernel<<<1, 1, 0, st>>>(ei_raw);
    convert_edges_kernel<<<EB, 256, 0, st>>>(ei_raw);
    init_csr_kernel<<<NB, 256, 0, st>>>();
    hist_kernel<<<EB, 256, 0, st>>>();
    scan_kernel<<<1, 1024, 0, st>>>();
    fill_kernel<<<EB, 256, 0, st>>>();

    // ---- Layer 1: hcat1 = [x@W1 | x@A1+b1] ----
    run_gemm(x, 0, W1, nullptr, BUF_HCAT1, 0,   NN, HH1, DIN, 1024, false, st);
    run_gemm(x, 0, A1, b1,      BUF_HCAT1, HH1, NN, HH1, DIN, 1024, false, st);
    att_dots_kernel<<<WB, 256, 0, st>>>(BUF_HCAT1, HH1, 1024, att_src1, att_dst1);
    init_ms_kernel<<<NB, 256, 0, st>>>();
    edge_max_kernel<<<EB, 256, 0, st>>>();
    edge_exp_kernel<<<EB, 256, 0, st>>>();
    aggregate_kernel<HH1, true><<<NN, HH1 / 4, 0, st>>>(
        BUF_HCAT1, 0, HH1, 1024, b_conv1, BUF_H1);

    // ---- Layer 2: hcat2 = [h1@W2 | h1@A2+b2] ----
    run_gemm(nullptr, BUF_H1, W2, nullptr, BUF_HCAT2, 0,   NN, HH2, HH1, 512, false, st);
    run_gemm(nullptr, BUF_H1, A2, b2,      BUF_HCAT2, HH2, NN, HH2, HH1, 512, false, st);
    att_dots_kernel<<<WB, 256, 0, st>>>(BUF_HCAT2, HH2, 512, att_src2, att_dst2);
    init_ms_kernel<<<NB, 256, 0, st>>>();
    edge_max_kernel<<<EB, 256, 0, st>>>();
    edge_exp_kernel<<<EB, 256, 0, st>>>();
    aggregate_kernel<HH2, false><<<NN, HH2 / 4, 0, st>>>(
        BUF_HCAT2, 0, HH2, 512, b_conv2, BUF_H2);

    // ---- MLP ----
    run_gemm(nullptr, BUF_H2,   Hw1, Hb1, BUF_MLP0, 0, NN, HH2, HH2, HH2, true, st);
    run_gemm(nullptr, BUF_MLP0, Hw2, Hb2, BUF_MLP1, 0, NN, HH2, HH2, HH2, true, st);
    run_gemm(nullptr, BUF_MLP1, Hw3, Hb3, BUF_MLP0, 0, NN, HH2, HH2, HH2, true, st);

    // ---- Classifier + softmax ----
    fc_softmax_kernel<<<WB, 256, 0, st>>>(BUF_MLP0, fcw, fcb, out);
}